// round 15
// baseline (speedup 1.0000x reference)
#include <cuda_runtime.h>
#include <cuda_bf16.h>
#include <cuda_fp16.h>
#include <math.h>
#include <stdint.h>

// Problem constants
#define BB 8
#define NN 2048
#define CC 1024
#define HH 16
#define DD 64
#define MM (BB*NN)        // 16384 rows
#define HALFC (CC/2)

// Scratch (device globals: allocation-free per harness rules)
__device__ float  g_kmp2[128*CC];          // per-mblock raw-K column sums
__device__ float  g_km[BB*CC];             // [b][c] k-mean (includes 1/N)
__device__ float  g_z[128*NN];             // [bh][n]
__device__ float  g_invfreq[HALFC];
__device__ float2 g_rope[NN*HALFC];        // (cos, sin)

// fp16 GEMM operands
__device__ __half g_Ah[MM*CC];
__device__ __half g_Wh[3][CC*CC];
// bf16 attention operands
__device__ __nv_bfloat16 g_Qr[MM*CC];      // [m][c] roped q
__device__ __nv_bfloat16 g_Kr[MM*CC];      // [m][c] roped k (row-major)
__device__ __nv_bfloat16 g_Vbf[MM*CC];     // [m][c] v (row-major)
__device__ __nv_bfloat16 g_kv[128*DD*DD];  // [bh][d][e]
__device__ __nv_bfloat16 g_O16[MM*CC];     // attention output (pre-residual)

// ---------------------------------------------------------------------------
__global__ void init_invfreq_kernel() {
    int j = threadIdx.x;
    if (j < HALFC)
        g_invfreq[j] = (float)(1.0 / pow(10000.0, (double)(2 * j) / (double)CC));
}
__global__ __launch_bounds__(512) void init_rope_kernel() {
    int n = blockIdx.x;
    int j = threadIdx.x;
    float ang = (float)n * g_invfreq[j];
    float sv, cv;
    sincosf(ang, &sv, &cv);
    g_rope[n * HALFC + j] = make_float2(cv, sv);
}

// ---------------------------------------------------------------------------
__device__ __forceinline__ unsigned packbf2(float a, float b) {
    unsigned short lo = __bfloat16_as_ushort(__float2bfloat16(a));
    unsigned short hi = __bfloat16_as_ushort(__float2bfloat16(b));
    return (unsigned)lo | ((unsigned)hi << 16);
}
__device__ __forceinline__ unsigned packh2(float a, float b) {
    __half2 h = __floats2half2_rn(a, b);
    return *(unsigned*)&h;
}
__device__ __forceinline__ float bf_lo(unsigned u) {
    return __bfloat162float(__ushort_as_bfloat16((unsigned short)(u & 0xffff)));
}
__device__ __forceinline__ float bf_hi(unsigned u) {
    return __bfloat162float(__ushort_as_bfloat16((unsigned short)(u >> 16)));
}

// Grid-stride fp32->fp16 conversion; W loop converts all three per index (MLP).
#define CONV_BLOCKS 1184
__global__ __launch_bounds__(256) void conv_all_kernel(
    const float* __restrict__ x, const float* __restrict__ W0,
    const float* __restrict__ W1, const float* __restrict__ W2)
{
    const int T = CONV_BLOCKS * 256;
    int tid = blockIdx.x * 256 + threadIdx.x;
    const int NX4 = MM * CC / 4;
    const int NW4 = CC * CC / 4;
    for (int i = tid; i < NX4; i += T) {
        float4 v = __ldg((const float4*)x + i);
        uint2 u; u.x = packh2(v.x, v.y); u.y = packh2(v.z, v.w);
        *((uint2*)g_Ah + i) = u;
    }
    for (int i = tid; i < NW4; i += T) {
        float4 v0 = __ldg((const float4*)W0 + i);
        float4 v1 = __ldg((const float4*)W1 + i);
        float4 v2 = __ldg((const float4*)W2 + i);
        uint2 u0, u1, u2;
        u0.x = packh2(v0.x, v0.y); u0.y = packh2(v0.z, v0.w);
        u1.x = packh2(v1.x, v1.y); u1.y = packh2(v1.z, v1.w);
        u2.x = packh2(v2.x, v2.y); u2.y = packh2(v2.z, v2.w);
        *((uint2*)g_Wh[0] + i) = u0;
        *((uint2*)g_Wh[1] + i) = u1;
        *((uint2*)g_Wh[2] + i) = u2;
    }
}

// ---------------------------------------------------------------------------
// MMA helpers
__device__ __forceinline__ void ldsm4(unsigned* r, uint32_t addr) {
    asm volatile("ldmatrix.sync.aligned.m8n8.x4.shared.b16 {%0,%1,%2,%3},[%4];\n"
                 : "=r"(r[0]), "=r"(r[1]), "=r"(r[2]), "=r"(r[3]) : "r"(addr));
}
__device__ __forceinline__ void ldsm4t(unsigned* r, uint32_t addr) {
    asm volatile("ldmatrix.sync.aligned.m8n8.x4.trans.shared.b16 {%0,%1,%2,%3},[%4];\n"
                 : "=r"(r[0]), "=r"(r[1]), "=r"(r[2]), "=r"(r[3]) : "r"(addr));
}
// bf16 mma, fp32 acc (attention tail)
__device__ __forceinline__ void mma16816(float* d, const unsigned* a, const unsigned* b) {
    asm volatile("mma.sync.aligned.m16n8k16.row.col.f32.bf16.bf16.f32 "
                 "{%0,%1,%2,%3},{%4,%5,%6,%7},{%8,%9},{%0,%1,%2,%3};\n"
                 : "+f"(d[0]), "+f"(d[1]), "+f"(d[2]), "+f"(d[3])
                 : "r"(a[0]), "r"(a[1]), "r"(a[2]), "r"(a[3]), "r"(b[0]), "r"(b[1]));
}
// fp16 mma, fp16 acc (main GEMM)
__device__ __forceinline__ void mma16816h(unsigned* d, const unsigned* a, const unsigned* b) {
    asm volatile("mma.sync.aligned.m16n8k16.row.col.f16.f16.f16.f16 "
                 "{%0,%1},{%2,%3,%4,%5},{%6,%7},{%0,%1};\n"
                 : "+r"(d[0]), "+r"(d[1])
                 : "r"(a[0]), "r"(a[1]), "r"(a[2]), "r"(a[3]), "r"(b[0]), "r"(b[1]));
}
__device__ __forceinline__ void cp16(uint32_t sp, const void* gp) {
    asm volatile("cp.async.cg.shared.global [%0],[%1],16;\n" :: "r"(sp), "l"(gp));
}

// ---------------------------------------------------------------------------
// Main QKV GEMM (fp16 in, fp16 acc). Tile 128x128, 4 warps (2x2 of 64x64),
// BK=64, 2-stage cp.async, 3 CTAs/SM. blockIdx.z = which.
#define SA 72
#define OPSZ (128 * SA * 2)        // 18432 per operand per stage
#define STGSZ (2 * OPSZ)           // 36864
#define GEMM_SMEM (2 * STGSZ)      // 73728
#define NIT 16

__global__ __launch_bounds__(128, 3) void gemm_mma_kernel(
    const float* __restrict__ bq, const float* __restrict__ bk,
    const float* __restrict__ bv)
{
    extern __shared__ __half sm[];
    const int which = blockIdx.z;
    const float* __restrict__ bias = (which == 0) ? bq : (which == 1) ? bk : bv;
    const bool gel = (which < 2);
    const __half* __restrict__ Wp = g_Wh[which];

    const int t = threadIdx.x;
    const int lane = t & 31, warp = t >> 5;
    const int wm = warp & 1, wn = warp >> 1;     // 2x2 warps, warp tile 64x64
    const int m0 = blockIdx.y * 128, n0 = blockIdx.x * 128;

    const uint32_t sBase = (uint32_t)__cvta_generic_to_shared(sm);

    unsigned acch[4][8][2];        // fp16x2 accumulators: 4 m16 x 8 n8
    #pragma unroll
    for (int mt = 0; mt < 4; mt++)
        #pragma unroll
        for (int j = 0; j < 8; j++) { acch[mt][j][0] = 0u; acch[mt][j][1] = 0u; }

    auto prefetch = [&](int it, int stg) {
        int kk = it << 6;
        uint32_t sA = sBase + stg * STGSZ;
        uint32_t sW = sA + OPSZ;
        #pragma unroll
        for (int i = 0; i < 16; i++) {
            int c = t + i * 128;                 // 0..2047 16B chunks
            int isW = c >> 10, cc = c & 1023;
            int row = cc >> 3, seg = cc & 7;
            const __half* gp = isW
                ? Wp + (size_t)(n0 + row) * CC + kk + seg * 8
                : g_Ah + (size_t)(m0 + row) * CC + kk + seg * 8;
            cp16((isW ? sW : sA) + (row * SA + seg * 8) * 2, gp);
        }
        asm volatile("cp.async.commit_group;\n");
    };

    const int aRow = lane & 15, aCol = (lane >> 4) << 3;
    const int bRow = (lane & 7) + ((lane >> 4) << 3), bCol = ((lane >> 3) & 1) << 3;

    prefetch(0, 0);

    #pragma unroll 1
    for (int it = 0; it < NIT; ++it) {
        asm volatile("cp.async.wait_group 0;\n");
        __syncthreads();
        if (it + 1 < NIT) prefetch(it + 1, (it + 1) & 1);

        const uint32_t sA = sBase + (it & 1) * STGSZ;
        const uint32_t sW = sA + OPSZ;
        #pragma unroll
        for (int ks = 0; ks < 4; ++ks) {
            unsigned a[4][4], bfr[4][4];
            #pragma unroll
            for (int mt = 0; mt < 4; ++mt)
                ldsm4(a[mt], sA + ((wm * 64 + mt * 16 + aRow) * SA + ks * 16 + aCol) * 2);
            #pragma unroll
            for (int nb = 0; nb < 4; ++nb)
                ldsm4(bfr[nb], sW + ((wn * 64 + nb * 16 + bRow) * SA + ks * 16 + bCol) * 2);
            #pragma unroll
            for (int mt = 0; mt < 4; ++mt)
                #pragma unroll
                for (int j = 0; j < 8; ++j)
                    mma16816h(acch[mt][j], a[mt], &bfr[j >> 1][(j & 1) * 2]);
        }
    }
    __syncthreads();     // smem free for epilogue staging

    const int gid = lane >> 2, tid2 = lane & 3;

    if (which == 0) {
        // Q: roped bf16 row-major writes only (z derives from Qr downstream)
        #pragma unroll
        for (int mt = 0; mt < 4; ++mt) {
            int rl = wm * 64 + mt * 16 + gid;
            int m_lo = m0 + rl, m_hi = m_lo + 8;
            int nlo = m_lo & 2047, nhi = m_hi & 2047;
            #pragma unroll
            for (int j = 0; j < 8; ++j) {
                int c = n0 + wn * 64 + j * 8 + tid2 * 2;
                float b0 = __ldg(&bias[c]), b1 = __ldg(&bias[c + 1]);
                float2 flo = __half22float2(*(__half2*)&acch[mt][j][0]);
                float2 fhi = __half22float2(*(__half2*)&acch[mt][j][1]);
                float y0 = flo.x + b0, y1 = flo.y + b1;
                float y2 = fhi.x + b0, y3 = fhi.y + b1;
                y0 = 0.5f * y0 * (1.f + erff(y0 * 0.7071067811865476f)) + 0.21f;
                y1 = 0.5f * y1 * (1.f + erff(y1 * 0.7071067811865476f)) + 0.21f;
                y2 = 0.5f * y2 * (1.f + erff(y2 * 0.7071067811865476f)) + 0.21f;
                y3 = 0.5f * y3 * (1.f + erff(y3 * 0.7071067811865476f)) + 0.21f;
                float2 rlc = g_rope[nlo * HALFC + (c >> 1)];
                float2 rhc = g_rope[nhi * HALFC + (c >> 1)];
                *(unsigned*)&g_Qr[(size_t)m_lo * CC + c] =
                    packbf2(y0 * rlc.x - y1 * rlc.y, y1 * rlc.x + y0 * rlc.y);
                *(unsigned*)&g_Qr[(size_t)m_hi * CC + c] =
                    packbf2(y2 * rhc.x - y3 * rhc.y, y3 * rhc.x + y2 * rhc.y);
            }
        }
    } else {
        // K: bias+gelu+ksum+rope -> g_Kr row-major. V: bias -> g_Vbf row-major.
        float* ksmem = (float*)sm;                    // [4 warps][128 cols]
        __nv_bfloat16* __restrict__ dst = gel ? g_Kr : g_Vbf;
        if (gel) {                                    // zero the 4x128 slots
            #pragma unroll
            for (int i = 0; i < 4; ++i) ksmem[t + i * 128] = 0.f;
        }
        __syncthreads();
        float ke[8], ko[8];
        #pragma unroll
        for (int j = 0; j < 8; ++j) { ke[j] = 0.f; ko[j] = 0.f; }

        #pragma unroll
        for (int mt = 0; mt < 4; ++mt) {
            int rl = wm * 64 + mt * 16 + gid;
            int m_lo = m0 + rl, m_hi = m_lo + 8;
            int nlo = m_lo & 2047, nhi = m_hi & 2047;
            #pragma unroll
            for (int j = 0; j < 8; ++j) {
                int c = n0 + wn * 64 + j * 8 + tid2 * 2;
                float b0 = __ldg(&bias[c]), b1 = __ldg(&bias[c + 1]);
                float2 flo = __half22float2(*(__half2*)&acch[mt][j][0]);
                float2 fhi = __half22float2(*(__half2*)&acch[mt][j][1]);
                float y0 = flo.x + b0, y1 = flo.y + b1;
                float y2 = fhi.x + b0, y3 = fhi.y + b1;
                if (gel) {   // K path
                    y0 = 0.5f * y0 * (1.f + erff(y0 * 0.7071067811865476f)) + 0.21f;
                    y1 = 0.5f * y1 * (1.f + erff(y1 * 0.7071067811865476f)) + 0.21f;
                    y2 = 0.5f * y2 * (1.f + erff(y2 * 0.7071067811865476f)) + 0.21f;
                    y3 = 0.5f * y3 * (1.f + erff(y3 * 0.7071067811865476f)) + 0.21f;
                    ke[j] += y0 + y2;  ko[j] += y1 + y3;
                    float2 rlc = g_rope[nlo * HALFC + (c >> 1)];
                    float2 rhc = g_rope[nhi * HALFC + (c >> 1)];
                    float k0 = y0 * rlc.x - y1 * rlc.y, k1 = y1 * rlc.x + y0 * rlc.y;
                    float k2 = y2 * rhc.x - y3 * rhc.y, k3 = y3 * rhc.x + y2 * rhc.y;
                    y0 = k0; y1 = k1; y2 = k2; y3 = k3;
                }
                *(unsigned*)&dst[(size_t)m_lo * CC + c] = packbf2(y0, y1);
                *(unsigned*)&dst[(size_t)m_hi * CC + c] = packbf2(y2, y3);
            }
        }
        if (gel) {
            #pragma unroll
            for (int j = 0; j < 8; ++j) {
                float se = ke[j], so = ko[j];
                se += __shfl_down_sync(0xffffffffu, se, 4);
                se += __shfl_down_sync(0xffffffffu, se, 8);
                se += __shfl_down_sync(0xffffffffu, se, 16);
                so += __shfl_down_sync(0xffffffffu, so, 4);
                so += __shfl_down_sync(0xffffffffu, so, 8);
                so += __shfl_down_sync(0xffffffffu, so, 16);
                if (lane < 4) {
                    int lc = wn * 64 + j * 8 + tid2 * 2;
                    ksmem[warp * 128 + lc]     = se;
                    ksmem[warp * 128 + lc + 1] = so;
                }
            }
        }
        __syncthreads();
        if (gel) {
            float s = ksmem[t] + ksmem[128 + t] + ksmem[256 + t] + ksmem[384 + t];
            g_kmp2[(size_t)blockIdx.y * CC + n0 + t] = s;
        }
    }
}

// ---------------------------------------------------------------------------
// kmean: reduce per-mblock partials, apply 1/N
__global__ __launch_bounds__(256) void kmean_kernel() {
    int b = blockIdx.x;
    for (int c = threadIdx.x; c < CC; c += 256) {
        float s = 0.f;
        #pragma unroll
        for (int mb = 0; mb < 16; mb++)
            s += g_kmp2[(size_t)(b * 16 + mb) * CC + c];
        g_km[b * CC + c] = s * (1.f / (float)NN);
    }
}

// z[bh][n] = 1/(qr . R_n(km) + 1e-6)  (rotation identity: == 1/(q.km + eps))
__global__ __launch_bounds__(256) void z_kernel() {
    int m0 = blockIdx.x * 16;
    int b = m0 >> 11;
    __shared__ float kms[CC];
    for (int i = threadIdx.x; i < CC; i += 256) kms[i] = g_km[b * CC + i];
    __syncthreads();
    int r = threadIdx.x >> 4, h = threadIdx.x & 15;
    int m = m0 + r;
    int n = m & 2047;
    const float2* rp = g_rope + (size_t)n * HALFC + h * 32;
    const unsigned* qp = (const unsigned*)(g_Qr + (size_t)m * CC + h * 64);
    float s = 0.f;
    #pragma unroll
    for (int j = 0; j < 32; j++) {
        float2 cs = rp[j];
        float k0 = kms[h * 64 + 2 * j], k1 = kms[h * 64 + 2 * j + 1];
        float kr0 = k0 * cs.x - k1 * cs.y;
        float kr1 = k1 * cs.x + k0 * cs.y;
        unsigned q2 = qp[j];
        s += bf_lo(q2) * kr0 + bf_hi(q2) * kr1;
    }
    g_z[(size_t)(b * 16 + h) * NN + n] = 1.f / (s + 1e-6f);
}

// ---------------------------------------------------------------------------
// kv[d][e] = (1/N) sum_n Kr[n,d] * V[n,e]  via trans-ldmatrix fragments.
// 256 threads: two warp-groups, split-N halves, smem reduce.
#define KSA 72
#define KVOP (64 * KSA * 2)            // 9216 per operand per stage
#define KVSTG (2 * KVOP)               // 18432
#define KV_SMEM (6 * KVSTG)            // 110592 (3 stages x 2 groups)
__global__ __launch_bounds__(256) void kv_mma_kernel() {
    extern __shared__ __nv_bfloat16 ksm[];
    int bh = blockIdx.x;
    int h = bh & 15, b = bh >> 4;
    int t = threadIdx.x, lane = t & 31, warp = t >> 5;
    int grp = warp >> 2, wi = warp & 3;
    const __nv_bfloat16* Ap = g_Kr + (size_t)b * NN * CC + (size_t)grp * 1024 * CC + h * 64;
    const __nv_bfloat16* Bp = g_Vbf + (size_t)b * NN * CC + (size_t)grp * 1024 * CC + h * 64;
    const uint32_t s0 = (uint32_t)__cvta_generic_to_shared(ksm) + grp * 3 * KVSTG;
    int gt = t & 127;

    float acc[8][4];
    #pragma unroll
    for (int j = 0; j < 8; j++)
        #pragma unroll
        for (int r = 0; r < 4; r++) acc[j][r] = 0.f;

    auto pf = [&](int it, int stg) {
        int nn = it * 64;
        uint32_t sa = s0 + stg * KVSTG;
        uint32_t sb = sa + KVOP;
        #pragma unroll
        for (int i = 0; i < 4; i++) {
            int ii = gt + i * 128;
            int row = ii >> 3, seg = ii & 7;
            cp16(sa + (row * KSA + seg * 8) * 2, Ap + (size_t)(nn + row) * CC + seg * 8);
            cp16(sb + (row * KSA + seg * 8) * 2, Bp + (size_t)(nn + row) * CC + seg * 8);
        }
        asm volatile("cp.async.commit_group;\n");
    };
    const int atRow = (lane & 7) + ((lane >> 4) << 3), atCol = ((lane >> 3) & 1) << 3;
    const int btRow = (lane & 7) + (((lane >> 3) & 1) << 3), btCol = (lane >> 4) << 3;

    pf(0, 0);
    pf(1, 1);
    #pragma unroll 1
    for (int it = 0; it < 16; ++it) {
        if (it < 15) asm volatile("cp.async.wait_group 1;\n");
        else         asm volatile("cp.async.wait_group 0;\n");
        __syncthreads();
        if (it + 2 < 16) pf(it + 2, (it + 2) % 3);
        const uint32_t sa = s0 + (it % 3) * KVSTG;
        const uint32_t sb = sa + KVOP;
        #pragma unroll
        for (int ks = 0; ks < 4; ++ks) {
            unsigned a[4], bf[4][4];
            ldsm4t(a, sa + ((ks * 16 + atRow) * KSA + wi * 16 + atCol) * 2);
            #pragma unroll
            for (int np = 0; np < 4; ++np)
                ldsm4t(bf[np], sb + ((ks * 16 + btRow) * KSA + np * 16 + btCol) * 2);
            #pragma unroll
            for (int j = 0; j < 8; ++j)
                mma16816(acc[j], a, &bf[j >> 1][(j & 1) * 2]);
        }
    }
    __syncthreads();
    float* red = (float*)ksm;
    const int gid = lane >> 2, tid2 = lane & 3;
    int d_lo = wi * 16 + gid, d_hi = d_lo + 8;
    if (grp == 1) {
        #pragma unroll
        for (int j = 0; j < 8; ++j) {
            int e = j * 8 + tid2 * 2;
            red[d_lo * 64 + e]     = acc[j][0];
            red[d_lo * 64 + e + 1] = acc[j][1];
            red[d_hi * 64 + e]     = acc[j][2];
            red[d_hi * 64 + e + 1] = acc[j][3];
        }
    }
    __syncthreads();
    if (grp == 0) {
        const float sc = 1.f / (float)NN;
        #pragma unroll
        for (int j = 0; j < 8; ++j) {
            int e = j * 8 + tid2 * 2;
            *(unsigned*)&g_kv[(size_t)bh * 4096 + d_lo * 64 + e] =
                packbf2((acc[j][0] + red[d_lo * 64 + e]) * sc,
                        (acc[j][1] + red[d_lo * 64 + e + 1]) * sc);
            *(unsigned*)&g_kv[(size_t)bh * 4096 + d_hi * 64 + e] =
                packbf2((acc[j][2] + red[d_hi * 64 + e]) * sc,
                        (acc[j][3] + red[d_hi * 64 + e + 1]) * sc);
        }
    }
}

// ---------------------------------------------------------------------------
// out[m][h*64+e] = z[m,h] * sum_d Qr[m][h*64+d] * kv[d][e]
__global__ __launch_bounds__(256) void out_mma_kernel() {
    int bh = blockIdx.x;
    int h = bh & 15, b = bh >> 4;
    int m0 = b * NN + blockIdx.y * 128;
    __shared__ __align__(16) __nv_bfloat16 sA[128 * 72];
    __shared__ __align__(16) __nv_bfloat16 sB[64 * 72];
    __shared__ float zv[128];
    int t = threadIdx.x, lane = t & 31, warp = t >> 5;
    const uint32_t a0 = (uint32_t)__cvta_generic_to_shared(sA);
    const uint32_t b0 = (uint32_t)__cvta_generic_to_shared(sB);

    #pragma unroll
    for (int i = 0; i < 4; i++) {
        int ii = t + i * 256;
        int row = ii >> 3, seg = ii & 7;
        cp16(a0 + (row * 72 + seg * 8) * 2,
             g_Qr + (size_t)(m0 + row) * CC + h * 64 + seg * 8);
    }
    #pragma unroll
    for (int i = 0; i < 2; i++) {
        int ii = t + i * 256;
        int row = ii >> 3, seg = ii & 7;
        cp16(b0 + (row * 72 + seg * 8) * 2,
             g_kv + (size_t)bh * 4096 + row * 64 + seg * 8);
    }
    asm volatile("cp.async.commit_group;\n");

    if (t < 128) zv[t] = g_z[(size_t)bh * NN + ((m0 + t) & 2047)];
    asm volatile("cp.async.wait_group 0;\n");
    __syncthreads();

    const int aRow = lane & 15, aCol = (lane >> 4) << 3;
    const int btRow = (lane & 7) + (((lane >> 3) & 1) << 3), btCol = (lane >> 4) << 3;
    float acc[8][4];
    #pragma unroll
    for (int j = 0; j < 8; j++)
        #pragma unroll
        for (int r = 0; r < 4; r++) acc[j][r] = 0.f;

    #pragma unroll
    for (int ks = 0; ks < 4; ++ks) {
        unsigned a[4], bf[4][4];
        ldsm4(a, a0 + ((warp * 16 + aRow) * 72 + ks * 16 + aCol) * 2);
        #pragma unroll
        for (int np = 0; np < 4; ++np)
            ldsm4t(bf[np], b0 + ((ks * 16 + btRow) * 72 + np * 16 + btCol) * 2);
        #pragma unroll
        for (int j = 0; j < 8; ++j)
            mma16816(acc[j], a, &bf[j >> 1][(j & 1) * 2]);
    }

    const int gid = lane >> 2, tid2 = lane & 3;
    int rl = warp * 16 + gid;
    int m_lo = m0 + rl, m_hi = m_lo + 8;
    float zl = zv[rl], zh = zv[rl + 8];
    #pragma unroll
    for (int j = 0; j < 8; ++j) {
        int c = h * 64 + j * 8 + tid2 * 2;
        *(unsigned*)&g_O16[(size_t)m_lo * CC + c] = packbf2(acc[j][0] * zl, acc[j][1] * zl);
        *(unsigned*)&g_O16[(size_t)m_hi * CC + c] = packbf2(acc[j][2] * zh, acc[j][3] * zh);
    }
}

// ---------------------------------------------------------------------------
__global__ __launch_bounds__(256) void ln_kernel(
    const float* __restrict__ x, const float* __restrict__ gamma,
    const float* __restrict__ beta, float* __restrict__ out)
{
    int row = blockIdx.x;
    int t = threadIdx.x;
    uint2 ou = *(const uint2*)&g_O16[(size_t)row * CC + t * 4];
    float4 xv = *(const float4*)&x[(size_t)row * CC + t * 4];
    float4 r;
    r.x = xv.x + bf_lo(ou.x);
    r.y = xv.y + bf_hi(ou.x);
    r.z = xv.z + bf_lo(ou.y);
    r.w = xv.w + bf_hi(ou.y);
    float s  = r.x + r.y + r.z + r.w;
    float sq = r.x * r.x + r.y * r.y + r.z * r.z + r.w * r.w;
    #pragma unroll
    for (int off = 16; off; off >>= 1) {
        s  += __shfl_xor_sync(0xffffffffu, s, off);
        sq += __shfl_xor_sync(0xffffffffu, sq, off);
    }
    __shared__ float ss[8], ssq[8];
    __shared__ float mean_s, rstd_s;
    int w = t >> 5, lane = t & 31;
    if (lane == 0) { ss[w] = s; ssq[w] = sq; }
    __syncthreads();
    if (t == 0) {
        float S = 0.f, SQ = 0.f;
        #pragma unroll
        for (int i = 0; i < 8; i++) { S += ss[i]; SQ += ssq[i]; }
        float mean = S * (1.f / (float)CC);
        float var  = SQ * (1.f / (float)CC) - mean * mean;
        mean_s = mean;
        rstd_s = rsqrtf(var + 1e-12f);
    }
    __syncthreads();
    float mean = mean_s, rstd = rstd_s;
    float4 g  = *(const float4*)&gamma[t * 4];
    float4 be = *(const float4*)&beta[t * 4];
    float4 o;
    o.x = (r.x - mean) * rstd * g.x + be.x;
    o.y = (r.y - mean) * rstd * g.y + be.y;
    o.z = (r.z - mean) * rstd * g.z + be.z;
    o.w = (r.w - mean) * rstd * g.w + be.w;
    *(float4*)&out[(size_t)row * CC + t * 4] = o;
}

// ---------------------------------------------------------------------------
extern "C" void kernel_launch(void* const* d_in, const int* in_sizes, int n_in,
                              void* d_out, int out_size) {
    const float* x     = (const float*)d_in[0];
    const float* Wq    = (const float*)d_in[1];
    const float* bq    = (const float*)d_in[2];
    const float* Wk    = (const float*)d_in[3];
    const float* bk    = (const float*)d_in[4];
    const float* Wv    = (const float*)d_in[5];
    const float* bv    = (const float*)d_in[6];
    const float* gamma = (const float*)d_in[7];
    const float* beta  = (const float*)d_in[8];
    float* out = (float*)d_out;

    init_invfreq_kernel<<<1, 512>>>();
    init_rope_kernel<<<NN, 512>>>();
    conv_all_kernel<<<CONV_BLOCKS, 256>>>(x, Wq, Wk, Wv);

    cudaFuncSetAttribute(gemm_mma_kernel,
                         cudaFuncAttributeMaxDynamicSharedMemorySize, GEMM_SMEM);
    dim3 ggrid(CC / 128, MM / 128, 3);
    gemm_mma_kernel<<<ggrid, 128, GEMM_SMEM>>>(bq, bk, bv);

    kmean_kernel<<<BB, 256>>>();
    z_kernel<<<MM / 16, 256>>>();
    cudaFuncSetAttribute(kv_mma_kernel,
                         cudaFuncAttributeMaxDynamicSharedMemorySize, KV_SMEM);
    kv_mma_kernel<<<128, 256, KV_SMEM>>>();
    out_mma_kernel<<<dim3(128, NN / 128), 256>>>();
    ln_kernel<<<MM, 256>>>(x, gamma, beta, out);
}

// round 16
// speedup vs baseline: 1.1789x; 1.1789x over previous
#include <cuda_runtime.h>
#include <cuda_bf16.h>
#include <cuda_fp16.h>
#include <math.h>
#include <stdint.h>

// Problem constants
#define BB 8
#define NN 2048
#define CC 1024
#define HH 16
#define DD 64
#define MM (BB*NN)        // 16384 rows
#define HALFC (CC/2)

// Scratch (device globals: allocation-free per harness rules)
__device__ float  g_kmp2[128*CC];          // per-mblock raw-K column sums
__device__ float  g_km[BB*CC];             // [b][c] k-mean (includes 1/N)
__device__ float  g_invfreq[HALFC];
__device__ float2 g_rope[NN*HALFC];        // (cos, sin)

// fp16 GEMM operands
__device__ __half g_Ah[MM*CC];
__device__ __half g_Wh[3][CC*CC];
// bf16 attention operands
__device__ __nv_bfloat16 g_Qraw[MM*CC];    // [m][c] post-gelu raw q (for z)
__device__ __nv_bfloat16 g_Qr[MM*CC];      // [m][c] roped q
__device__ __nv_bfloat16 g_Kr[MM*CC];      // [m][c] roped k (row-major)
__device__ __nv_bfloat16 g_Vbf[MM*CC];     // [m][c] v (row-major)
__device__ __nv_bfloat16 g_kv[128*DD*DD];  // [bh][d][e]
__device__ __nv_bfloat16 g_O16[MM*CC];     // attention output (pre-residual)

// ---------------------------------------------------------------------------
__global__ void init_invfreq_kernel() {
    int j = threadIdx.x;
    if (j < HALFC)
        g_invfreq[j] = (float)(1.0 / pow(10000.0, (double)(2 * j) / (double)CC));
}
__global__ __launch_bounds__(512) void init_rope_kernel() {
    int n = blockIdx.x;
    int j = threadIdx.x;
    float ang = (float)n * g_invfreq[j];
    float sv, cv;
    sincosf(ang, &sv, &cv);
    g_rope[n * HALFC + j] = make_float2(cv, sv);
}

// ---------------------------------------------------------------------------
__device__ __forceinline__ unsigned packbf2(float a, float b) {
    unsigned short lo = __bfloat16_as_ushort(__float2bfloat16(a));
    unsigned short hi = __bfloat16_as_ushort(__float2bfloat16(b));
    return (unsigned)lo | ((unsigned)hi << 16);
}
__device__ __forceinline__ unsigned packh2(float a, float b) {
    __half2 h = __floats2half2_rn(a, b);
    return *(unsigned*)&h;
}
__device__ __forceinline__ float bf_lo(unsigned u) {
    return __bfloat162float(__ushort_as_bfloat16((unsigned short)(u & 0xffff)));
}
__device__ __forceinline__ float bf_hi(unsigned u) {
    return __bfloat162float(__ushort_as_bfloat16((unsigned short)(u >> 16)));
}

// Grid-stride fp32->fp16 conversion; W loop converts all three per index (MLP).
#define CONV_BLOCKS 1184
__global__ __launch_bounds__(256) void conv_all_kernel(
    const float* __restrict__ x, const float* __restrict__ W0,
    const float* __restrict__ W1, const float* __restrict__ W2)
{
    const int T = CONV_BLOCKS * 256;
    int tid = blockIdx.x * 256 + threadIdx.x;
    const int NX4 = MM * CC / 4;
    const int NW4 = CC * CC / 4;
    for (int i = tid; i < NX4; i += T) {
        float4 v = __ldg((const float4*)x + i);
        uint2 u; u.x = packh2(v.x, v.y); u.y = packh2(v.z, v.w);
        *((uint2*)g_Ah + i) = u;
    }
    for (int i = tid; i < NW4; i += T) {
        float4 v0 = __ldg((const float4*)W0 + i);
        float4 v1 = __ldg((const float4*)W1 + i);
        float4 v2 = __ldg((const float4*)W2 + i);
        uint2 u0, u1, u2;
        u0.x = packh2(v0.x, v0.y); u0.y = packh2(v0.z, v0.w);
        u1.x = packh2(v1.x, v1.y); u1.y = packh2(v1.z, v1.w);
        u2.x = packh2(v2.x, v2.y); u2.y = packh2(v2.z, v2.w);
        *((uint2*)g_Wh[0] + i) = u0;
        *((uint2*)g_Wh[1] + i) = u1;
        *((uint2*)g_Wh[2] + i) = u2;
    }
}

// ---------------------------------------------------------------------------
// MMA helpers
__device__ __forceinline__ void ldsm4(unsigned* r, uint32_t addr) {
    asm volatile("ldmatrix.sync.aligned.m8n8.x4.shared.b16 {%0,%1,%2,%3},[%4];\n"
                 : "=r"(r[0]), "=r"(r[1]), "=r"(r[2]), "=r"(r[3]) : "r"(addr));
}
__device__ __forceinline__ void ldsm4t(unsigned* r, uint32_t addr) {
    asm volatile("ldmatrix.sync.aligned.m8n8.x4.trans.shared.b16 {%0,%1,%2,%3},[%4];\n"
                 : "=r"(r[0]), "=r"(r[1]), "=r"(r[2]), "=r"(r[3]) : "r"(addr));
}
// bf16 mma, fp32 acc (attention tail)
__device__ __forceinline__ void mma16816(float* d, const unsigned* a, const unsigned* b) {
    asm volatile("mma.sync.aligned.m16n8k16.row.col.f32.bf16.bf16.f32 "
                 "{%0,%1,%2,%3},{%4,%5,%6,%7},{%8,%9},{%0,%1,%2,%3};\n"
                 : "+f"(d[0]), "+f"(d[1]), "+f"(d[2]), "+f"(d[3])
                 : "r"(a[0]), "r"(a[1]), "r"(a[2]), "r"(a[3]), "r"(b[0]), "r"(b[1]));
}
// fp16 mma, fp16 acc (main GEMM)
__device__ __forceinline__ void mma16816h(unsigned* d, const unsigned* a, const unsigned* b) {
    asm volatile("mma.sync.aligned.m16n8k16.row.col.f16.f16.f16.f16 "
                 "{%0,%1},{%2,%3,%4,%5},{%6,%7},{%0,%1};\n"
                 : "+r"(d[0]), "+r"(d[1])
                 : "r"(a[0]), "r"(a[1]), "r"(a[2]), "r"(a[3]), "r"(b[0]), "r"(b[1]));
}
__device__ __forceinline__ void cp16(uint32_t sp, const void* gp) {
    asm volatile("cp.async.cg.shared.global [%0],[%1],16;\n" :: "r"(sp), "l"(gp));
}

// ---------------------------------------------------------------------------
// Main QKV GEMM (fp16 in, fp16 acc). Tile 128x128, 4 warps (2x2 of 64x64),
// BK=64, 2-stage cp.async, 3 CTAs/SM. blockIdx.z = which.
#define SA 72
#define OPSZ (128 * SA * 2)        // 18432 per operand per stage
#define STGSZ (2 * OPSZ)           // 36864
#define GEMM_SMEM (2 * STGSZ)      // 73728
#define NIT 16

__global__ __launch_bounds__(128, 3) void gemm_mma_kernel(
    const float* __restrict__ bq, const float* __restrict__ bk,
    const float* __restrict__ bv)
{
    extern __shared__ __half sm[];
    const int which = blockIdx.z;
    const float* __restrict__ bias = (which == 0) ? bq : (which == 1) ? bk : bv;
    const bool gel = (which < 2);
    const __half* __restrict__ Wp = g_Wh[which];

    const int t = threadIdx.x;
    const int lane = t & 31, warp = t >> 5;
    const int wm = warp & 1, wn = warp >> 1;     // 2x2 warps, warp tile 64x64
    const int m0 = blockIdx.y * 128, n0 = blockIdx.x * 128;

    const uint32_t sBase = (uint32_t)__cvta_generic_to_shared(sm);

    unsigned acch[4][8][2];        // fp16x2 accumulators: 4 m16 x 8 n8
    #pragma unroll
    for (int mt = 0; mt < 4; mt++)
        #pragma unroll
        for (int j = 0; j < 8; j++) { acch[mt][j][0] = 0u; acch[mt][j][1] = 0u; }

    auto prefetch = [&](int it, int stg) {
        int kk = it << 6;
        uint32_t sA = sBase + stg * STGSZ;
        uint32_t sW = sA + OPSZ;
        #pragma unroll
        for (int i = 0; i < 16; i++) {
            int c = t + i * 128;                 // 0..2047 16B chunks
            int isW = c >> 10, cc = c & 1023;
            int row = cc >> 3, seg = cc & 7;
            const __half* gp = isW
                ? Wp + (size_t)(n0 + row) * CC + kk + seg * 8
                : g_Ah + (size_t)(m0 + row) * CC + kk + seg * 8;
            cp16((isW ? sW : sA) + (row * SA + seg * 8) * 2, gp);
        }
        asm volatile("cp.async.commit_group;\n");
    };

    const int aRow = lane & 15, aCol = (lane >> 4) << 3;
    const int bRow = (lane & 7) + ((lane >> 4) << 3), bCol = ((lane >> 3) & 1) << 3;

    prefetch(0, 0);

    #pragma unroll 1
    for (int it = 0; it < NIT; ++it) {
        asm volatile("cp.async.wait_group 0;\n");
        __syncthreads();
        if (it + 1 < NIT) prefetch(it + 1, (it + 1) & 1);

        const uint32_t sA = sBase + (it & 1) * STGSZ;
        const uint32_t sW = sA + OPSZ;
        #pragma unroll
        for (int ks = 0; ks < 4; ++ks) {
            unsigned a[4][4], bfr[4][4];
            #pragma unroll
            for (int mt = 0; mt < 4; ++mt)
                ldsm4(a[mt], sA + ((wm * 64 + mt * 16 + aRow) * SA + ks * 16 + aCol) * 2);
            #pragma unroll
            for (int nb = 0; nb < 4; ++nb)
                ldsm4(bfr[nb], sW + ((wn * 64 + nb * 16 + bRow) * SA + ks * 16 + bCol) * 2);
            #pragma unroll
            for (int mt = 0; mt < 4; ++mt)
                #pragma unroll
                for (int j = 0; j < 8; ++j)
                    mma16816h(acch[mt][j], a[mt], &bfr[j >> 1][(j & 1) * 2]);
        }
    }
    __syncthreads();     // smem free for epilogue staging

    const int gid = lane >> 2, tid2 = lane & 3;

    if (which == 0) {
        // Q: raw bf16 + roped bf16 row-major writes
        #pragma unroll
        for (int mt = 0; mt < 4; ++mt) {
            int rl = wm * 64 + mt * 16 + gid;
            int m_lo = m0 + rl, m_hi = m_lo + 8;
            int nlo = m_lo & 2047, nhi = m_hi & 2047;
            #pragma unroll
            for (int j = 0; j < 8; ++j) {
                int c = n0 + wn * 64 + j * 8 + tid2 * 2;
                float b0 = __ldg(&bias[c]), b1 = __ldg(&bias[c + 1]);
                float2 flo = __half22float2(*(__half2*)&acch[mt][j][0]);
                float2 fhi = __half22float2(*(__half2*)&acch[mt][j][1]);
                float y0 = flo.x + b0, y1 = flo.y + b1;
                float y2 = fhi.x + b0, y3 = fhi.y + b1;
                y0 = 0.5f * y0 * (1.f + erff(y0 * 0.7071067811865476f)) + 0.21f;
                y1 = 0.5f * y1 * (1.f + erff(y1 * 0.7071067811865476f)) + 0.21f;
                y2 = 0.5f * y2 * (1.f + erff(y2 * 0.7071067811865476f)) + 0.21f;
                y3 = 0.5f * y3 * (1.f + erff(y3 * 0.7071067811865476f)) + 0.21f;
                *(unsigned*)&g_Qraw[(size_t)m_lo * CC + c] = packbf2(y0, y1);
                *(unsigned*)&g_Qraw[(size_t)m_hi * CC + c] = packbf2(y2, y3);
                float2 rlc = g_rope[nlo * HALFC + (c >> 1)];
                float2 rhc = g_rope[nhi * HALFC + (c >> 1)];
                *(unsigned*)&g_Qr[(size_t)m_lo * CC + c] =
                    packbf2(y0 * rlc.x - y1 * rlc.y, y1 * rlc.x + y0 * rlc.y);
                *(unsigned*)&g_Qr[(size_t)m_hi * CC + c] =
                    packbf2(y2 * rhc.x - y3 * rhc.y, y3 * rhc.x + y2 * rhc.y);
            }
        }
    } else {
        // K: bias+gelu+ksum+rope -> g_Kr row-major. V: bias -> g_Vbf row-major.
        float* ksmem = (float*)sm;                    // [4 warps][128 cols]
        __nv_bfloat16* __restrict__ dst = gel ? g_Kr : g_Vbf;
        if (gel) {                                    // zero the 4x128 slots
            #pragma unroll
            for (int i = 0; i < 4; ++i) ksmem[t + i * 128] = 0.f;
        }
        __syncthreads();
        float ke[8], ko[8];
        #pragma unroll
        for (int j = 0; j < 8; ++j) { ke[j] = 0.f; ko[j] = 0.f; }

        #pragma unroll
        for (int mt = 0; mt < 4; ++mt) {
            int rl = wm * 64 + mt * 16 + gid;
            int m_lo = m0 + rl, m_hi = m_lo + 8;
            int nlo = m_lo & 2047, nhi = m_hi & 2047;
            #pragma unroll
            for (int j = 0; j < 8; ++j) {
                int c = n0 + wn * 64 + j * 8 + tid2 * 2;
                float b0 = __ldg(&bias[c]), b1 = __ldg(&bias[c + 1]);
                float2 flo = __half22float2(*(__half2*)&acch[mt][j][0]);
                float2 fhi = __half22float2(*(__half2*)&acch[mt][j][1]);
                float y0 = flo.x + b0, y1 = flo.y + b1;
                float y2 = fhi.x + b0, y3 = fhi.y + b1;
                if (gel) {   // K path
                    y0 = 0.5f * y0 * (1.f + erff(y0 * 0.7071067811865476f)) + 0.21f;
                    y1 = 0.5f * y1 * (1.f + erff(y1 * 0.7071067811865476f)) + 0.21f;
                    y2 = 0.5f * y2 * (1.f + erff(y2 * 0.7071067811865476f)) + 0.21f;
                    y3 = 0.5f * y3 * (1.f + erff(y3 * 0.7071067811865476f)) + 0.21f;
                    ke[j] += y0 + y2;  ko[j] += y1 + y3;
                    float2 rlc = g_rope[nlo * HALFC + (c >> 1)];
                    float2 rhc = g_rope[nhi * HALFC + (c >> 1)];
                    float k0 = y0 * rlc.x - y1 * rlc.y, k1 = y1 * rlc.x + y0 * rlc.y;
                    float k2 = y2 * rhc.x - y3 * rhc.y, k3 = y3 * rhc.x + y2 * rhc.y;
                    y0 = k0; y1 = k1; y2 = k2; y3 = k3;
                }
                *(unsigned*)&dst[(size_t)m_lo * CC + c] = packbf2(y0, y1);
                *(unsigned*)&dst[(size_t)m_hi * CC + c] = packbf2(y2, y3);
            }
        }
        if (gel) {
            #pragma unroll
            for (int j = 0; j < 8; ++j) {
                float se = ke[j], so = ko[j];
                se += __shfl_down_sync(0xffffffffu, se, 4);
                se += __shfl_down_sync(0xffffffffu, se, 8);
                se += __shfl_down_sync(0xffffffffu, se, 16);
                so += __shfl_down_sync(0xffffffffu, so, 4);
                so += __shfl_down_sync(0xffffffffu, so, 8);
                so += __shfl_down_sync(0xffffffffu, so, 16);
                if (lane < 4) {
                    int lc = wn * 64 + j * 8 + tid2 * 2;
                    ksmem[warp * 128 + lc]     = se;
                    ksmem[warp * 128 + lc + 1] = so;
                }
            }
        }
        __syncthreads();
        if (gel) {
            float s = ksmem[t] + ksmem[128 + t] + ksmem[256 + t] + ksmem[384 + t];
            g_kmp2[(size_t)blockIdx.y * CC + n0 + t] = s;
        }
    }
}

// ---------------------------------------------------------------------------
// kmean: reduce per-mblock partials, apply 1/N
__global__ __launch_bounds__(256) void kmean_kernel() {
    int b = blockIdx.x;
    for (int c = threadIdx.x; c < CC; c += 256) {
        float s = 0.f;
        #pragma unroll
        for (int mb = 0; mb < 16; mb++)
            s += g_kmp2[(size_t)(b * 16 + mb) * CC + c];
        g_km[b * CC + c] = s * (1.f / (float)NN);
    }
}

// ---------------------------------------------------------------------------
// kv[d][e] = (1/N) sum_n Kr[n,d] * V[n,e]  via trans-ldmatrix fragments.
// 256 threads: two warp-groups, split-N halves, smem reduce.
#define KSA 72
#define KVOP (64 * KSA * 2)            // 9216 per operand per stage
#define KVSTG (2 * KVOP)               // 18432
#define KV_SMEM (6 * KVSTG)            // 110592 (3 stages x 2 groups)
__global__ __launch_bounds__(256) void kv_mma_kernel() {
    extern __shared__ __nv_bfloat16 ksm[];
    int bh = blockIdx.x;
    int h = bh & 15, b = bh >> 4;
    int t = threadIdx.x, lane = t & 31, warp = t >> 5;
    int grp = warp >> 2, wi = warp & 3;
    const __nv_bfloat16* Ap = g_Kr + (size_t)b * NN * CC + (size_t)grp * 1024 * CC + h * 64;
    const __nv_bfloat16* Bp = g_Vbf + (size_t)b * NN * CC + (size_t)grp * 1024 * CC + h * 64;
    const uint32_t s0 = (uint32_t)__cvta_generic_to_shared(ksm) + grp * 3 * KVSTG;
    int gt = t & 127;

    float acc[8][4];
    #pragma unroll
    for (int j = 0; j < 8; j++)
        #pragma unroll
        for (int r = 0; r < 4; r++) acc[j][r] = 0.f;

    auto pf = [&](int it, int stg) {
        int nn = it * 64;
        uint32_t sa = s0 + stg * KVSTG;
        uint32_t sb = sa + KVOP;
        #pragma unroll
        for (int i = 0; i < 4; i++) {
            int ii = gt + i * 128;
            int row = ii >> 3, seg = ii & 7;
            cp16(sa + (row * KSA + seg * 8) * 2, Ap + (size_t)(nn + row) * CC + seg * 8);
            cp16(sb + (row * KSA + seg * 8) * 2, Bp + (size_t)(nn + row) * CC + seg * 8);
        }
        asm volatile("cp.async.commit_group;\n");
    };
    const int atRow = (lane & 7) + ((lane >> 4) << 3), atCol = ((lane >> 3) & 1) << 3;
    const int btRow = (lane & 7) + (((lane >> 3) & 1) << 3), btCol = (lane >> 4) << 3;

    pf(0, 0);
    pf(1, 1);
    #pragma unroll 1
    for (int it = 0; it < 16; ++it) {
        if (it < 15) asm volatile("cp.async.wait_group 1;\n");
        else         asm volatile("cp.async.wait_group 0;\n");
        __syncthreads();
        if (it + 2 < 16) pf(it + 2, (it + 2) % 3);
        const uint32_t sa = s0 + (it % 3) * KVSTG;
        const uint32_t sb = sa + KVOP;
        #pragma unroll
        for (int ks = 0; ks < 4; ++ks) {
            unsigned a[4], bf[4][4];
            ldsm4t(a, sa + ((ks * 16 + atRow) * KSA + wi * 16 + atCol) * 2);
            #pragma unroll
            for (int np = 0; np < 4; ++np)
                ldsm4t(bf[np], sb + ((ks * 16 + btRow) * KSA + np * 16 + btCol) * 2);
            #pragma unroll
            for (int j = 0; j < 8; ++j)
                mma16816(acc[j], a, &bf[j >> 1][(j & 1) * 2]);
        }
    }
    __syncthreads();
    float* red = (float*)ksm;
    const int gid = lane >> 2, tid2 = lane & 3;
    int d_lo = wi * 16 + gid, d_hi = d_lo + 8;
    if (grp == 1) {
        #pragma unroll
        for (int j = 0; j < 8; ++j) {
            int e = j * 8 + tid2 * 2;
            red[d_lo * 64 + e]     = acc[j][0];
            red[d_lo * 64 + e + 1] = acc[j][1];
            red[d_hi * 64 + e]     = acc[j][2];
            red[d_hi * 64 + e + 1] = acc[j][3];
        }
    }
    __syncthreads();
    if (grp == 0) {
        const float sc = 1.f / (float)NN;
        #pragma unroll
        for (int j = 0; j < 8; ++j) {
            int e = j * 8 + tid2 * 2;
            *(unsigned*)&g_kv[(size_t)bh * 4096 + d_lo * 64 + e] =
                packbf2((acc[j][0] + red[d_lo * 64 + e]) * sc,
                        (acc[j][1] + red[d_lo * 64 + e + 1]) * sc);
            *(unsigned*)&g_kv[(size_t)bh * 4096 + d_hi * 64 + e] =
                packbf2((acc[j][2] + red[d_hi * 64 + e]) * sc,
                        (acc[j][3] + red[d_hi * 64 + e + 1]) * sc);
        }
    }
}

// ---------------------------------------------------------------------------
// out[m][h*64+e] = z[m,h] * sum_d Qr[m][h*64+d] * kv[d][e]
// z = 1/(qraw . km + 1e-6), computed in cp.async shadow from g_Qraw.
// Each block processes 256 rows in two 128-row halves (kv/kms amortized).
__global__ __launch_bounds__(256) void out_mma_kernel() {
    int bh = blockIdx.x;
    int h = bh & 15, b = bh >> 4;
    int mbase = b * NN + blockIdx.y * 256;
    __shared__ __align__(16) __nv_bfloat16 sA[128 * 72];
    __shared__ __align__(16) __nv_bfloat16 sB[64 * 72];
    __shared__ float kms[64];
    __shared__ float zv[128];
    int t = threadIdx.x, lane = t & 31, warp = t >> 5;
    const uint32_t a0 = (uint32_t)__cvta_generic_to_shared(sA);
    const uint32_t b0 = (uint32_t)__cvta_generic_to_shared(sB);

    // kv tile (shared across both halves) + first A tile
    #pragma unroll
    for (int i = 0; i < 2; i++) {
        int ii = t + i * 256;
        int row = ii >> 3, seg = ii & 7;
        cp16(b0 + (row * 72 + seg * 8) * 2,
             g_kv + (size_t)bh * 4096 + row * 64 + seg * 8);
    }
    if (t < 64) kms[t] = g_km[b * CC + h * 64 + t];

    const int aRow = lane & 15, aCol = (lane >> 4) << 3;
    const int btRow = (lane & 7) + (((lane >> 3) & 1) << 3), btCol = (lane >> 4) << 3;
    const int gid = lane >> 2, tid2 = lane & 3;

    #pragma unroll
    for (int i = 0; i < 4; i++) {
        int ii = t + i * 256;
        int row = ii >> 3, seg = ii & 7;
        cp16(a0 + (row * 72 + seg * 8) * 2,
             g_Qr + (size_t)(mbase + row) * CC + h * 64 + seg * 8);
    }
    asm volatile("cp.async.commit_group;\n");
    __syncthreads();              // kms visible to all

    #pragma unroll 1
    for (int ig = 0; ig < 2; ++ig) {
        int m0 = mbase + ig * 128;
        // z computation in cp.async shadow
        if (t < 128) {
            const __nv_bfloat16* qp = g_Qraw + (size_t)(m0 + t) * CC + h * 64;
            float s = 0.f;
            #pragma unroll
            for (int i = 0; i < 8; i++) {
                uint4 v = *(const uint4*)(qp + i * 8);
                unsigned u[4] = {v.x, v.y, v.z, v.w};
                #pragma unroll
                for (int k = 0; k < 4; k++) {
                    s += bf_lo(u[k]) * kms[i * 8 + k * 2] +
                         bf_hi(u[k]) * kms[i * 8 + k * 2 + 1];
                }
            }
            zv[t] = 1.f / (s + 1e-6f);
        }
        asm volatile("cp.async.wait_group 0;\n");
        __syncthreads();

        float acc[8][4];
        #pragma unroll
        for (int j = 0; j < 8; j++)
            #pragma unroll
            for (int r = 0; r < 4; r++) acc[j][r] = 0.f;

        #pragma unroll
        for (int ks = 0; ks < 4; ++ks) {
            unsigned a[4], bf[4][4];
            ldsm4(a, a0 + ((warp * 16 + aRow) * 72 + ks * 16 + aCol) * 2);
            #pragma unroll
            for (int np = 0; np < 4; ++np)
                ldsm4t(bf[np], b0 + ((ks * 16 + btRow) * 72 + np * 16 + btCol) * 2);
            #pragma unroll
            for (int j = 0; j < 8; ++j)
                mma16816(acc[j], a, &bf[j >> 1][(j & 1) * 2]);
        }

        int rl = warp * 16 + gid;
        int m_lo = m0 + rl, m_hi = m_lo + 8;
        float zl = zv[rl], zh = zv[rl + 8];
        #pragma unroll
        for (int j = 0; j < 8; ++j) {
            int c = h * 64 + j * 8 + tid2 * 2;
            *(unsigned*)&g_O16[(size_t)m_lo * CC + c] = packbf2(acc[j][0] * zl, acc[j][1] * zl);
            *(unsigned*)&g_O16[(size_t)m_hi * CC + c] = packbf2(acc[j][2] * zh, acc[j][3] * zh);
        }
        __syncthreads();          // sA / zv reusable
        if (ig == 0) {            // prefetch second A tile
            #pragma unroll
            for (int i = 0; i < 4; i++) {
                int ii = t + i * 256;
                int row = ii >> 3, seg = ii & 7;
                cp16(a0 + (row * 72 + seg * 8) * 2,
                     g_Qr + (size_t)(mbase + 128 + row) * CC + h * 64 + seg * 8);
            }
            asm volatile("cp.async.commit_group;\n");
        }
    }
}

// ---------------------------------------------------------------------------
__global__ __launch_bounds__(256) void ln_kernel(
    const float* __restrict__ x, const float* __restrict__ gamma,
    const float* __restrict__ beta, float* __restrict__ out)
{
    int row = blockIdx.x;
    int t = threadIdx.x;
    uint2 ou = *(const uint2*)&g_O16[(size_t)row * CC + t * 4];
    float4 xv = *(const float4*)&x[(size_t)row * CC + t * 4];
    float4 r;
    r.x = xv.x + bf_lo(ou.x);
    r.y = xv.y + bf_hi(ou.x);
    r.z = xv.z + bf_lo(ou.y);
    r.w = xv.w + bf_hi(ou.y);
    float s  = r.x + r.y + r.z + r.w;
    float sq = r.x * r.x + r.y * r.y + r.z * r.z + r.w * r.w;
    #pragma unroll
    for (int off = 16; off; off >>= 1) {
        s  += __shfl_xor_sync(0xffffffffu, s, off);
        sq += __shfl_xor_sync(0xffffffffu, sq, off);
    }
    __shared__ float ss[8], ssq[8];
    __shared__ float mean_s, rstd_s;
    int w = t >> 5, lane = t & 31;
    if (lane == 0) { ss[w] = s; ssq[w] = sq; }
    __syncthreads();
    if (t == 0) {
        float S = 0.f, SQ = 0.f;
        #pragma unroll
        for (int i = 0; i < 8; i++) { S += ss[i]; SQ += ssq[i]; }
        float mean = S * (1.f / (float)CC);
        float var  = SQ * (1.f / (float)CC) - mean * mean;
        mean_s = mean;
        rstd_s = rsqrtf(var + 1e-12f);
    }
    __syncthreads();
    float mean = mean_s, rstd = rstd_s;
    float4 g  = *(const float4*)&gamma[t * 4];
    float4 be = *(const float4*)&beta[t * 4];
    float4 o;
    o.x = (r.x - mean) * rstd * g.x + be.x;
    o.y = (r.y - mean) * rstd * g.y + be.y;
    o.z = (r.z - mean) * rstd * g.z + be.z;
    o.w = (r.w - mean) * rstd * g.w + be.w;
    *(float4*)&out[(size_t)row * CC + t * 4] = o;
}

// ---------------------------------------------------------------------------
extern "C" void kernel_launch(void* const* d_in, const int* in_sizes, int n_in,
                              void* d_out, int out_size) {
    const float* x     = (const float*)d_in[0];
    const float* Wq    = (const float*)d_in[1];
    const float* bq    = (const float*)d_in[2];
    const float* Wk    = (const float*)d_in[3];
    const float* bk    = (const float*)d_in[4];
    const float* Wv    = (const float*)d_in[5];
    const float* bv    = (const float*)d_in[6];
    const float* gamma = (const float*)d_in[7];
    const float* beta  = (const float*)d_in[8];
    float* out = (float*)d_out;

    init_invfreq_kernel<<<1, 512>>>();
    init_rope_kernel<<<NN, 512>>>();
    conv_all_kernel<<<CONV_BLOCKS, 256>>>(x, Wq, Wk, Wv);

    cudaFuncSetAttribute(gemm_mma_kernel,
                         cudaFuncAttributeMaxDynamicSharedMemorySize, GEMM_SMEM);
    dim3 ggrid(CC / 128, MM / 128, 3);
    gemm_mma_kernel<<<ggrid, 128, GEMM_SMEM>>>(bq, bk, bv);

    kmean_kernel<<<BB, 256>>>();
    cudaFuncSetAttribute(kv_mma_kernel,
                         cudaFuncAttributeMaxDynamicSharedMemorySize, KV_SMEM);
    kv_mma_kernel<<<128, 256, KV_SMEM>>>();
    out_mma_kernel<<<dim3(128, NN / 256), 256>>>();
    ln_kernel<<<MM, 256>>>(x, gamma, beta, out);
}

// round 17
// speedup vs baseline: 1.1804x; 1.0013x over previous
#include <cuda_runtime.h>
#include <cuda_bf16.h>
#include <cuda_fp16.h>
#include <math.h>
#include <stdint.h>

// Problem constants
#define BB 8
#define NN 2048
#define CC 1024
#define HH 16
#define DD 64
#define MM (BB*NN)        // 16384 rows
#define HALFC (CC/2)

// Scratch (device globals: allocation-free per harness rules)
__device__ float  g_kmp2[128*CC];          // per-mblock raw-K column sums
__device__ float  g_km[BB*CC];             // [b][c] k-mean (includes 1/N)
__device__ float  g_invfreq[HALFC];
__device__ float2 g_rope[NN*HALFC];        // (cos, sin)

// fp16 GEMM operands
__device__ __half g_Ah[MM*CC];
__device__ __half g_Wh[3][CC*CC];
// bf16 attention operands
__device__ __nv_bfloat16 g_Qraw[MM*CC];    // [m][c] post-gelu raw q (for z)
__device__ __nv_bfloat16 g_Qr[MM*CC];      // [m][c] roped q
__device__ __nv_bfloat16 g_Kr[MM*CC];      // [m][c] roped k (row-major)
__device__ __nv_bfloat16 g_Vbf[MM*CC];     // [m][c] v (row-major)
__device__ __nv_bfloat16 g_kv[128*DD*DD];  // [bh][d][e]
__device__ __nv_bfloat16 g_O16[MM*CC];     // attention output (pre-residual)

// ---------------------------------------------------------------------------
__global__ void init_invfreq_kernel() {
    int j = threadIdx.x;
    if (j < HALFC)
        g_invfreq[j] = (float)(1.0 / pow(10000.0, (double)(2 * j) / (double)CC));
}

// ---------------------------------------------------------------------------
__device__ __forceinline__ unsigned packbf2(float a, float b) {
    unsigned short lo = __bfloat16_as_ushort(__float2bfloat16(a));
    unsigned short hi = __bfloat16_as_ushort(__float2bfloat16(b));
    return (unsigned)lo | ((unsigned)hi << 16);
}
__device__ __forceinline__ unsigned packh2(float a, float b) {
    __half2 h = __floats2half2_rn(a, b);
    return *(unsigned*)&h;
}
__device__ __forceinline__ float bf_lo(unsigned u) {
    return __bfloat162float(__ushort_as_bfloat16((unsigned short)(u & 0xffff)));
}
__device__ __forceinline__ float bf_hi(unsigned u) {
    return __bfloat162float(__ushort_as_bfloat16((unsigned short)(u >> 16)));
}

// Grid-stride prep: rope table + fp32->fp16 conversions (x and all three W).
#define CONV_BLOCKS 1184
__global__ __launch_bounds__(256) void conv_all_kernel(
    const float* __restrict__ x, const float* __restrict__ W0,
    const float* __restrict__ W1, const float* __restrict__ W2)
{
    const int T = CONV_BLOCKS * 256;
    int tid = blockIdx.x * 256 + threadIdx.x;
    // rope table (ALU-bound; overlaps the memory-bound conversions below)
    for (int i = tid; i < NN * HALFC; i += T) {
        int n = i >> 9, j = i & 511;
        float ang = (float)n * g_invfreq[j];
        float sv, cv;
        sincosf(ang, &sv, &cv);
        g_rope[i] = make_float2(cv, sv);
    }
    const int NX4 = MM * CC / 4;
    const int NW4 = CC * CC / 4;
    for (int i = tid; i < NX4; i += T) {
        float4 v = __ldg((const float4*)x + i);
        uint2 u; u.x = packh2(v.x, v.y); u.y = packh2(v.z, v.w);
        *((uint2*)g_Ah + i) = u;
    }
    for (int i = tid; i < NW4; i += T) {
        float4 v0 = __ldg((const float4*)W0 + i);
        float4 v1 = __ldg((const float4*)W1 + i);
        float4 v2 = __ldg((const float4*)W2 + i);
        uint2 u0, u1, u2;
        u0.x = packh2(v0.x, v0.y); u0.y = packh2(v0.z, v0.w);
        u1.x = packh2(v1.x, v1.y); u1.y = packh2(v1.z, v1.w);
        u2.x = packh2(v2.x, v2.y); u2.y = packh2(v2.z, v2.w);
        *((uint2*)g_Wh[0] + i) = u0;
        *((uint2*)g_Wh[1] + i) = u1;
        *((uint2*)g_Wh[2] + i) = u2;
    }
}

// ---------------------------------------------------------------------------
// MMA helpers
__device__ __forceinline__ void ldsm4(unsigned* r, uint32_t addr) {
    asm volatile("ldmatrix.sync.aligned.m8n8.x4.shared.b16 {%0,%1,%2,%3},[%4];\n"
                 : "=r"(r[0]), "=r"(r[1]), "=r"(r[2]), "=r"(r[3]) : "r"(addr));
}
__device__ __forceinline__ void ldsm4t(unsigned* r, uint32_t addr) {
    asm volatile("ldmatrix.sync.aligned.m8n8.x4.trans.shared.b16 {%0,%1,%2,%3},[%4];\n"
                 : "=r"(r[0]), "=r"(r[1]), "=r"(r[2]), "=r"(r[3]) : "r"(addr));
}
// bf16 mma, fp32 acc (attention tail)
__device__ __forceinline__ void mma16816(float* d, const unsigned* a, const unsigned* b) {
    asm volatile("mma.sync.aligned.m16n8k16.row.col.f32.bf16.bf16.f32 "
                 "{%0,%1,%2,%3},{%4,%5,%6,%7},{%8,%9},{%0,%1,%2,%3};\n"
                 : "+f"(d[0]), "+f"(d[1]), "+f"(d[2]), "+f"(d[3])
                 : "r"(a[0]), "r"(a[1]), "r"(a[2]), "r"(a[3]), "r"(b[0]), "r"(b[1]));
}
// fp16 mma, fp16 acc (main GEMM)
__device__ __forceinline__ void mma16816h(unsigned* d, const unsigned* a, const unsigned* b) {
    asm volatile("mma.sync.aligned.m16n8k16.row.col.f16.f16.f16.f16 "
                 "{%0,%1},{%2,%3,%4,%5},{%6,%7},{%0,%1};\n"
                 : "+r"(d[0]), "+r"(d[1])
                 : "r"(a[0]), "r"(a[1]), "r"(a[2]), "r"(a[3]), "r"(b[0]), "r"(b[1]));
}
__device__ __forceinline__ void cp16(uint32_t sp, const void* gp) {
    asm volatile("cp.async.cg.shared.global [%0],[%1],16;\n" :: "r"(sp), "l"(gp));
}

// ---------------------------------------------------------------------------
// Main QKV GEMM (fp16 in, fp16 acc). Tile 128x128, 4 warps (2x2 of 64x64),
// BK=64, 2-stage cp.async, 3 CTAs/SM. blockIdx.z = which.
#define SA 72
#define OPSZ (128 * SA * 2)        // 18432 per operand per stage
#define STGSZ (2 * OPSZ)           // 36864
#define GEMM_SMEM (2 * STGSZ)      // 73728
#define NIT 16

__global__ __launch_bounds__(128, 3) void gemm_mma_kernel(
    const float* __restrict__ bq, const float* __restrict__ bk,
    const float* __restrict__ bv)
{
    extern __shared__ __half sm[];
    const int which = blockIdx.z;
    const float* __restrict__ bias = (which == 0) ? bq : (which == 1) ? bk : bv;
    const bool gel = (which < 2);
    const __half* __restrict__ Wp = g_Wh[which];

    const int t = threadIdx.x;
    const int lane = t & 31, warp = t >> 5;
    const int wm = warp & 1, wn = warp >> 1;     // 2x2 warps, warp tile 64x64
    const int m0 = blockIdx.y * 128, n0 = blockIdx.x * 128;

    const uint32_t sBase = (uint32_t)__cvta_generic_to_shared(sm);

    unsigned acch[4][8][2];        // fp16x2 accumulators: 4 m16 x 8 n8
    #pragma unroll
    for (int mt = 0; mt < 4; mt++)
        #pragma unroll
        for (int j = 0; j < 8; j++) { acch[mt][j][0] = 0u; acch[mt][j][1] = 0u; }

    auto prefetch = [&](int it, int stg) {
        int kk = it << 6;
        uint32_t sA = sBase + stg * STGSZ;
        uint32_t sW = sA + OPSZ;
        #pragma unroll
        for (int i = 0; i < 16; i++) {
            int c = t + i * 128;                 // 0..2047 16B chunks
            int isW = c >> 10, cc = c & 1023;
            int row = cc >> 3, seg = cc & 7;
            const __half* gp = isW
                ? Wp + (size_t)(n0 + row) * CC + kk + seg * 8
                : g_Ah + (size_t)(m0 + row) * CC + kk + seg * 8;
            cp16((isW ? sW : sA) + (row * SA + seg * 8) * 2, gp);
        }
        asm volatile("cp.async.commit_group;\n");
    };

    const int aRow = lane & 15, aCol = (lane >> 4) << 3;
    const int bRow = (lane & 7) + ((lane >> 4) << 3), bCol = ((lane >> 3) & 1) << 3;

    prefetch(0, 0);

    #pragma unroll 1
    for (int it = 0; it < NIT; ++it) {
        asm volatile("cp.async.wait_group 0;\n");
        __syncthreads();
        if (it + 1 < NIT) prefetch(it + 1, (it + 1) & 1);

        const uint32_t sA = sBase + (it & 1) * STGSZ;
        const uint32_t sW = sA + OPSZ;
        #pragma unroll
        for (int ks = 0; ks < 4; ++ks) {
            unsigned a[4][4], bfr[4][4];
            #pragma unroll
            for (int mt = 0; mt < 4; ++mt)
                ldsm4(a[mt], sA + ((wm * 64 + mt * 16 + aRow) * SA + ks * 16 + aCol) * 2);
            #pragma unroll
            for (int nb = 0; nb < 4; ++nb)
                ldsm4(bfr[nb], sW + ((wn * 64 + nb * 16 + bRow) * SA + ks * 16 + bCol) * 2);
            #pragma unroll
            for (int mt = 0; mt < 4; ++mt)
                #pragma unroll
                for (int j = 0; j < 8; ++j)
                    mma16816h(acch[mt][j], a[mt], &bfr[j >> 1][(j & 1) * 2]);
        }
    }
    __syncthreads();     // smem free for epilogue staging

    const int gid = lane >> 2, tid2 = lane & 3;

    if (which == 0) {
        // Q: raw bf16 + roped bf16 row-major writes
        #pragma unroll
        for (int mt = 0; mt < 4; ++mt) {
            int rl = wm * 64 + mt * 16 + gid;
            int m_lo = m0 + rl, m_hi = m_lo + 8;
            int nlo = m_lo & 2047, nhi = m_hi & 2047;
            #pragma unroll
            for (int j = 0; j < 8; ++j) {
                int c = n0 + wn * 64 + j * 8 + tid2 * 2;
                float b0 = __ldg(&bias[c]), b1 = __ldg(&bias[c + 1]);
                float2 flo = __half22float2(*(__half2*)&acch[mt][j][0]);
                float2 fhi = __half22float2(*(__half2*)&acch[mt][j][1]);
                float y0 = flo.x + b0, y1 = flo.y + b1;
                float y2 = fhi.x + b0, y3 = fhi.y + b1;
                y0 = 0.5f * y0 * (1.f + erff(y0 * 0.7071067811865476f)) + 0.21f;
                y1 = 0.5f * y1 * (1.f + erff(y1 * 0.7071067811865476f)) + 0.21f;
                y2 = 0.5f * y2 * (1.f + erff(y2 * 0.7071067811865476f)) + 0.21f;
                y3 = 0.5f * y3 * (1.f + erff(y3 * 0.7071067811865476f)) + 0.21f;
                *(unsigned*)&g_Qraw[(size_t)m_lo * CC + c] = packbf2(y0, y1);
                *(unsigned*)&g_Qraw[(size_t)m_hi * CC + c] = packbf2(y2, y3);
                float2 rlc = g_rope[nlo * HALFC + (c >> 1)];
                float2 rhc = g_rope[nhi * HALFC + (c >> 1)];
                *(unsigned*)&g_Qr[(size_t)m_lo * CC + c] =
                    packbf2(y0 * rlc.x - y1 * rlc.y, y1 * rlc.x + y0 * rlc.y);
                *(unsigned*)&g_Qr[(size_t)m_hi * CC + c] =
                    packbf2(y2 * rhc.x - y3 * rhc.y, y3 * rhc.x + y2 * rhc.y);
            }
        }
    } else {
        // K: bias+gelu+ksum+rope -> g_Kr row-major. V: bias -> g_Vbf row-major.
        float* ksmem = (float*)sm;                    // [4 warps][128 cols]
        __nv_bfloat16* __restrict__ dst = gel ? g_Kr : g_Vbf;
        if (gel) {                                    // zero the 4x128 slots
            #pragma unroll
            for (int i = 0; i < 4; ++i) ksmem[t + i * 128] = 0.f;
        }
        __syncthreads();
        float ke[8], ko[8];
        #pragma unroll
        for (int j = 0; j < 8; ++j) { ke[j] = 0.f; ko[j] = 0.f; }

        #pragma unroll
        for (int mt = 0; mt < 4; ++mt) {
            int rl = wm * 64 + mt * 16 + gid;
            int m_lo = m0 + rl, m_hi = m_lo + 8;
            int nlo = m_lo & 2047, nhi = m_hi & 2047;
            #pragma unroll
            for (int j = 0; j < 8; ++j) {
                int c = n0 + wn * 64 + j * 8 + tid2 * 2;
                float b0 = __ldg(&bias[c]), b1 = __ldg(&bias[c + 1]);
                float2 flo = __half22float2(*(__half2*)&acch[mt][j][0]);
                float2 fhi = __half22float2(*(__half2*)&acch[mt][j][1]);
                float y0 = flo.x + b0, y1 = flo.y + b1;
                float y2 = fhi.x + b0, y3 = fhi.y + b1;
                if (gel) {   // K path
                    y0 = 0.5f * y0 * (1.f + erff(y0 * 0.7071067811865476f)) + 0.21f;
                    y1 = 0.5f * y1 * (1.f + erff(y1 * 0.7071067811865476f)) + 0.21f;
                    y2 = 0.5f * y2 * (1.f + erff(y2 * 0.7071067811865476f)) + 0.21f;
                    y3 = 0.5f * y3 * (1.f + erff(y3 * 0.7071067811865476f)) + 0.21f;
                    ke[j] += y0 + y2;  ko[j] += y1 + y3;
                    float2 rlc = g_rope[nlo * HALFC + (c >> 1)];
                    float2 rhc = g_rope[nhi * HALFC + (c >> 1)];
                    float k0 = y0 * rlc.x - y1 * rlc.y, k1 = y1 * rlc.x + y0 * rlc.y;
                    float k2 = y2 * rhc.x - y3 * rhc.y, k3 = y3 * rhc.x + y2 * rhc.y;
                    y0 = k0; y1 = k1; y2 = k2; y3 = k3;
                }
                *(unsigned*)&dst[(size_t)m_lo * CC + c] = packbf2(y0, y1);
                *(unsigned*)&dst[(size_t)m_hi * CC + c] = packbf2(y2, y3);
            }
        }
        if (gel) {
            #pragma unroll
            for (int j = 0; j < 8; ++j) {
                float se = ke[j], so = ko[j];
                se += __shfl_down_sync(0xffffffffu, se, 4);
                se += __shfl_down_sync(0xffffffffu, se, 8);
                se += __shfl_down_sync(0xffffffffu, se, 16);
                so += __shfl_down_sync(0xffffffffu, so, 4);
                so += __shfl_down_sync(0xffffffffu, so, 8);
                so += __shfl_down_sync(0xffffffffu, so, 16);
                if (lane < 4) {
                    int lc = wn * 64 + j * 8 + tid2 * 2;
                    ksmem[warp * 128 + lc]     = se;
                    ksmem[warp * 128 + lc + 1] = so;
                }
            }
        }
        __syncthreads();
        if (gel) {
            float s = ksmem[t] + ksmem[128 + t] + ksmem[256 + t] + ksmem[384 + t];
            g_kmp2[(size_t)blockIdx.y * CC + n0 + t] = s;
        }
    }
}

// ---------------------------------------------------------------------------
// kmean: reduce per-mblock partials, apply 1/N
__global__ __launch_bounds__(256) void kmean_kernel() {
    int b = blockIdx.x;
    for (int c = threadIdx.x; c < CC; c += 256) {
        float s = 0.f;
        #pragma unroll
        for (int mb = 0; mb < 16; mb++)
            s += g_kmp2[(size_t)(b * 16 + mb) * CC + c];
        g_km[b * CC + c] = s * (1.f / (float)NN);
    }
}

// ---------------------------------------------------------------------------
// kv[d][e] = (1/N) sum_n Kr[n,d] * V[n,e]  via trans-ldmatrix fragments.
// 256 threads: two warp-groups, split-N halves, smem reduce.
#define KSA 72
#define KVOP (64 * KSA * 2)            // 9216 per operand per stage
#define KVSTG (2 * KVOP)               // 18432
#define KV_SMEM (6 * KVSTG)            // 110592 (3 stages x 2 groups)
__global__ __launch_bounds__(256) void kv_mma_kernel() {
    extern __shared__ __nv_bfloat16 ksm[];
    int bh = blockIdx.x;
    int h = bh & 15, b = bh >> 4;
    int t = threadIdx.x, lane = t & 31, warp = t >> 5;
    int grp = warp >> 2, wi = warp & 3;
    const __nv_bfloat16* Ap = g_Kr + (size_t)b * NN * CC + (size_t)grp * 1024 * CC + h * 64;
    const __nv_bfloat16* Bp = g_Vbf + (size_t)b * NN * CC + (size_t)grp * 1024 * CC + h * 64;
    const uint32_t s0 = (uint32_t)__cvta_generic_to_shared(ksm) + grp * 3 * KVSTG;
    int gt = t & 127;

    float acc[8][4];
    #pragma unroll
    for (int j = 0; j < 8; j++)
        #pragma unroll
        for (int r = 0; r < 4; r++) acc[j][r] = 0.f;

    auto pf = [&](int it, int stg) {
        int nn = it * 64;
        uint32_t sa = s0 + stg * KVSTG;
        uint32_t sb = sa + KVOP;
        #pragma unroll
        for (int i = 0; i < 4; i++) {
            int ii = gt + i * 128;
            int row = ii >> 3, seg = ii & 7;
            cp16(sa + (row * KSA + seg * 8) * 2, Ap + (size_t)(nn + row) * CC + seg * 8);
            cp16(sb + (row * KSA + seg * 8) * 2, Bp + (size_t)(nn + row) * CC + seg * 8);
        }
        asm volatile("cp.async.commit_group;\n");
    };
    const int atRow = (lane & 7) + ((lane >> 4) << 3), atCol = ((lane >> 3) & 1) << 3;
    const int btRow = (lane & 7) + (((lane >> 3) & 1) << 3), btCol = (lane >> 4) << 3;

    pf(0, 0);
    pf(1, 1);
    #pragma unroll 1
    for (int it = 0; it < 16; ++it) {
        if (it < 15) asm volatile("cp.async.wait_group 1;\n");
        else         asm volatile("cp.async.wait_group 0;\n");
        __syncthreads();
        if (it + 2 < 16) pf(it + 2, (it + 2) % 3);
        const uint32_t sa = s0 + (it % 3) * KVSTG;
        const uint32_t sb = sa + KVOP;
        #pragma unroll
        for (int ks = 0; ks < 4; ++ks) {
            unsigned a[4], bf[4][4];
            ldsm4t(a, sa + ((ks * 16 + atRow) * KSA + wi * 16 + atCol) * 2);
            #pragma unroll
            for (int np = 0; np < 4; ++np)
                ldsm4t(bf[np], sb + ((ks * 16 + btRow) * KSA + np * 16 + btCol) * 2);
            #pragma unroll
            for (int j = 0; j < 8; ++j)
                mma16816(acc[j], a, &bf[j >> 1][(j & 1) * 2]);
        }
    }
    __syncthreads();
    float* red = (float*)ksm;
    const int gid = lane >> 2, tid2 = lane & 3;
    int d_lo = wi * 16 + gid, d_hi = d_lo + 8;
    if (grp == 1) {
        #pragma unroll
        for (int j = 0; j < 8; ++j) {
            int e = j * 8 + tid2 * 2;
            red[d_lo * 64 + e]     = acc[j][0];
            red[d_lo * 64 + e + 1] = acc[j][1];
            red[d_hi * 64 + e]     = acc[j][2];
            red[d_hi * 64 + e + 1] = acc[j][3];
        }
    }
    __syncthreads();
    if (grp == 0) {
        const float sc = 1.f / (float)NN;
        #pragma unroll
        for (int j = 0; j < 8; ++j) {
            int e = j * 8 + tid2 * 2;
            *(unsigned*)&g_kv[(size_t)bh * 4096 + d_lo * 64 + e] =
                packbf2((acc[j][0] + red[d_lo * 64 + e]) * sc,
                        (acc[j][1] + red[d_lo * 64 + e + 1]) * sc);
            *(unsigned*)&g_kv[(size_t)bh * 4096 + d_hi * 64 + e] =
                packbf2((acc[j][2] + red[d_hi * 64 + e]) * sc,
                        (acc[j][3] + red[d_hi * 64 + e + 1]) * sc);
        }
    }
}

// ---------------------------------------------------------------------------
// out[m][h*64+e] = z[m,h] * sum_d Qr[m][h*64+d] * kv[d][e]
// z = 1/(qraw . km + 1e-6), computed in cp.async shadow from g_Qraw.
// Each block processes 256 rows in two 128-row halves (kv/kms amortized).
__global__ __launch_bounds__(256) void out_mma_kernel() {
    int bh = blockIdx.x;
    int h = bh & 15, b = bh >> 4;
    int mbase = b * NN + blockIdx.y * 256;
    __shared__ __align__(16) __nv_bfloat16 sA[128 * 72];
    __shared__ __align__(16) __nv_bfloat16 sB[64 * 72];
    __shared__ float kms[64];
    __shared__ float zv[128];
    int t = threadIdx.x, lane = t & 31, warp = t >> 5;
    const uint32_t a0 = (uint32_t)__cvta_generic_to_shared(sA);
    const uint32_t b0 = (uint32_t)__cvta_generic_to_shared(sB);

    // kv tile (shared across both halves) + first A tile
    #pragma unroll
    for (int i = 0; i < 2; i++) {
        int ii = t + i * 256;
        int row = ii >> 3, seg = ii & 7;
        cp16(b0 + (row * 72 + seg * 8) * 2,
             g_kv + (size_t)bh * 4096 + row * 64 + seg * 8);
    }
    if (t < 64) kms[t] = g_km[b * CC + h * 64 + t];

    const int aRow = lane & 15, aCol = (lane >> 4) << 3;
    const int btRow = (lane & 7) + (((lane >> 3) & 1) << 3), btCol = (lane >> 4) << 3;
    const int gid = lane >> 2, tid2 = lane & 3;

    #pragma unroll
    for (int i = 0; i < 4; i++) {
        int ii = t + i * 256;
        int row = ii >> 3, seg = ii & 7;
        cp16(a0 + (row * 72 + seg * 8) * 2,
             g_Qr + (size_t)(mbase + row) * CC + h * 64 + seg * 8);
    }
    asm volatile("cp.async.commit_group;\n");
    __syncthreads();              // kms visible to all

    #pragma unroll 1
    for (int ig = 0; ig < 2; ++ig) {
        int m0 = mbase + ig * 128;
        // z computation in cp.async shadow
        if (t < 128) {
            const __nv_bfloat16* qp = g_Qraw + (size_t)(m0 + t) * CC + h * 64;
            float s = 0.f;
            #pragma unroll
            for (int i = 0; i < 8; i++) {
                uint4 v = *(const uint4*)(qp + i * 8);
                unsigned u[4] = {v.x, v.y, v.z, v.w};
                #pragma unroll
                for (int k = 0; k < 4; k++) {
                    s += bf_lo(u[k]) * kms[i * 8 + k * 2] +
                         bf_hi(u[k]) * kms[i * 8 + k * 2 + 1];
                }
            }
            zv[t] = 1.f / (s + 1e-6f);
        }
        asm volatile("cp.async.wait_group 0;\n");
        __syncthreads();

        float acc[8][4];
        #pragma unroll
        for (int j = 0; j < 8; j++)
            #pragma unroll
            for (int r = 0; r < 4; r++) acc[j][r] = 0.f;

        #pragma unroll
        for (int ks = 0; ks < 4; ++ks) {
            unsigned a[4], bf[4][4];
            ldsm4(a, a0 + ((warp * 16 + aRow) * 72 + ks * 16 + aCol) * 2);
            #pragma unroll
            for (int np = 0; np < 4; ++np)
                ldsm4t(bf[np], b0 + ((ks * 16 + btRow) * 72 + np * 16 + btCol) * 2);
            #pragma unroll
            for (int j = 0; j < 8; ++j)
                mma16816(acc[j], a, &bf[j >> 1][(j & 1) * 2]);
        }

        int rl = warp * 16 + gid;
        int m_lo = m0 + rl, m_hi = m_lo + 8;
        float zl = zv[rl], zh = zv[rl + 8];
        #pragma unroll
        for (int j = 0; j < 8; ++j) {
            int c = h * 64 + j * 8 + tid2 * 2;
            *(unsigned*)&g_O16[(size_t)m_lo * CC + c] = packbf2(acc[j][0] * zl, acc[j][1] * zl);
            *(unsigned*)&g_O16[(size_t)m_hi * CC + c] = packbf2(acc[j][2] * zh, acc[j][3] * zh);
        }
        __syncthreads();          // sA / zv reusable
        if (ig == 0) {            // prefetch second A tile
            #pragma unroll
            for (int i = 0; i < 4; i++) {
                int ii = t + i * 256;
                int row = ii >> 3, seg = ii & 7;
                cp16(a0 + (row * 72 + seg * 8) * 2,
                     g_Qr + (size_t)(mbase + 128 + row) * CC + h * 64 + seg * 8);
            }
            asm volatile("cp.async.commit_group;\n");
        }
    }
}

// ---------------------------------------------------------------------------
// residual + LayerNorm: 8 rows per block, one warp per row, shfl-only.
__global__ __launch_bounds__(256) void ln_kernel(
    const float* __restrict__ x, const float* __restrict__ gamma,
    const float* __restrict__ beta, float* __restrict__ out)
{
    int warp = threadIdx.x >> 5, lane = threadIdx.x & 31;
    size_t row = (size_t)blockIdx.x * 8 + warp;
    const uint2*  op = (const uint2*)&g_O16[row * CC];
    const float4* xp = (const float4*)&x[row * CC];
    float4 r[8];
    float s = 0.f, sq = 0.f;
    #pragma unroll
    for (int seg = 0; seg < 8; ++seg) {
        int i4 = seg * 32 + lane;
        uint2 ou = op[i4];
        float4 xv = xp[i4];
        float4 rr;
        rr.x = xv.x + bf_lo(ou.x);
        rr.y = xv.y + bf_hi(ou.x);
        rr.z = xv.z + bf_lo(ou.y);
        rr.w = xv.w + bf_hi(ou.y);
        r[seg] = rr;
        s  += rr.x + rr.y + rr.z + rr.w;
        sq += rr.x * rr.x + rr.y * rr.y + rr.z * rr.z + rr.w * rr.w;
    }
    #pragma unroll
    for (int off = 16; off; off >>= 1) {
        s  += __shfl_xor_sync(0xffffffffu, s, off);
        sq += __shfl_xor_sync(0xffffffffu, sq, off);
    }
    float mean = s * (1.f / (float)CC);
    float var  = sq * (1.f / (float)CC) - mean * mean;
    float rstd = rsqrtf(var + 1e-12f);
    float4* outp = (float4*)&out[row * CC];
    #pragma unroll
    for (int seg = 0; seg < 8; ++seg) {
        int i4 = seg * 32 + lane;
        float4 g  = __ldg((const float4*)gamma + i4);
        float4 be = __ldg((const float4*)beta + i4);
        float4 rr = r[seg];
        float4 o;
        o.x = (rr.x - mean) * rstd * g.x + be.x;
        o.y = (rr.y - mean) * rstd * g.y + be.y;
        o.z = (rr.z - mean) * rstd * g.z + be.z;
        o.w = (rr.w - mean) * rstd * g.w + be.w;
        outp[i4] = o;
    }
}

// ---------------------------------------------------------------------------
extern "C" void kernel_launch(void* const* d_in, const int* in_sizes, int n_in,
                              void* d_out, int out_size) {
    const float* x     = (const float*)d_in[0];
    const float* Wq    = (const float*)d_in[1];
    const float* bq    = (const float*)d_in[2];
    const float* Wk    = (const float*)d_in[3];
    const float* bk    = (const float*)d_in[4];
    const float* Wv    = (const float*)d_in[5];
    const float* bv    = (const float*)d_in[6];
    const float* gamma = (const float*)d_in[7];
    const float* beta  = (const float*)d_in[8];
    float* out = (float*)d_out;

    init_invfreq_kernel<<<1, 512>>>();
    conv_all_kernel<<<CONV_BLOCKS, 256>>>(x, Wq, Wk, Wv);

    cudaFuncSetAttribute(gemm_mma_kernel,
                         cudaFuncAttributeMaxDynamicSharedMemorySize, GEMM_SMEM);
    dim3 ggrid(CC / 128, MM / 128, 3);
    gemm_mma_kernel<<<ggrid, 128, GEMM_SMEM>>>(bq, bk, bv);

    kmean_kernel<<<BB, 256>>>();
    cudaFuncSetAttribute(kv_mma_kernel,
                         cudaFuncAttributeMaxDynamicSharedMemorySize, KV_SMEM);
    kv_mma_kernel<<<128, 256, KV_SMEM>>>();
    out_mma_kernel<<<dim3(128, NN / 256), 256>>>();
    ln_kernel<<<MM / 8, 256>>>(x, gamma, beta, out);
}